// round 14
// baseline (speedup 1.0000x reference)
#include <cuda_runtime.h>
#include <cuda_bf16.h>
#include <math.h>

#define BATCH 4
#define NPTS 16384
#define NVIEW 6
#define CCH 384
#define HH 32
#define WW 32
#define NPIX (HH*WW)
#define NCHUNK 128
#define CHPTS (NPTS/NCHUNK)   // 128

typedef unsigned long long u64;

// scratch (static device globals; no allocation anywhere)
__device__ __align__(16) float g_proj [BATCH*NVIEW*NPIX*64];   // 6.3 MB
__device__ __align__(16) float g_fused[BATCH*NPTS*32];         // 8 MB
__device__ __align__(16) float g_act  [BATCH*NPTS*64];         // 16 MB
__device__ __align__(16) float g_pv   [BATCH*NCHUNK*2048];     // 4 MB
__device__ __align__(16) float g_pa   [BATCH*NCHUNK*64];
__device__ __align__(16) float g_vl   [BATCH*2048];
__device__ __align__(16) float g_out  [BATCH*256];

// Branchless erf-based GELU: A&S 7.1.26 (max abs err ~1.5e-7), MUFU-backed.
__device__ __forceinline__ float geluf(float x){
    float xe = x*0.70710678118654752f;
    float ax = fabsf(xe);
    float t  = __fdividef(1.f, fmaf(0.3275911f, ax, 1.f));
    float p  = t*fmaf(t, fmaf(t, fmaf(t, fmaf(t, 1.061405429f, -1.453152027f),
                 1.421413741f), -0.284496736f), 0.254829592f);
    float e  = __expf(-ax*ax);
    float er = fmaf(-p, e, 1.f);
    er = copysignf(er, xe);
    return 0.5f*x*(1.f+er);
}
__device__ __forceinline__ float sigmoidf_(float x){
    return 1.f/(1.f+expf(-x));
}
// ---- packed f32x2 helpers (Blackwell; ptxas won't emit from C++) ----
__device__ __forceinline__ u64 pk2(float lo, float hi){
    u64 r; asm("mov.b64 %0,{%1,%2};" : "=l"(r) : "f"(lo), "f"(hi)); return r;
}
__device__ __forceinline__ void up2(u64 v, float& lo, float& hi){
    asm("mov.b64 {%0,%1},%2;" : "=f"(lo), "=f"(hi) : "l"(v));
}
__device__ __forceinline__ u64 fma2_(u64 a, u64 b, u64 c){
    u64 d; asm("fma.rn.f32x2 %0,%1,%2,%3;" : "=l"(d) : "l"(a), "l"(b), "l"(c)); return d;
}
__device__ __forceinline__ u64 mul2_(u64 a, u64 b){
    u64 d; asm("mul.rn.f32x2 %0,%1,%2;" : "=l"(d) : "l"(a), "l"(b)); return d;
}
__device__ __forceinline__ u64 add2_(u64 a, u64 b){
    u64 d; asm("add.rn.f32x2 %0,%1,%2;" : "=l"(d) : "l"(a), "l"(b)); return d;
}

// ---------------------------------------------------------------------------
// Kernel A: proj[bv][pix][o] = sum_c vf[bv][c][pix] * w1[c][o]
// grid (24,16): 64 pix x 4 output-groups of 16 per 256-thread block.
// ---------------------------------------------------------------------------
__global__ void __launch_bounds__(256) projK(const float* __restrict__ vf,
                                             const float* __restrict__ w1){
    __shared__ __align__(16) float w1s[96*64];
    int t = threadIdx.x;
    int bv  = blockIdx.x;
    int grp = t >> 6;                  // 0..3
    int pix = blockIdx.y*64 + (t & 63);
    int og  = grp*16;
    u64 acc[8];
    #pragma unroll
    for (int i=0;i<8;i++) acc[i]=0ull;
    const float* vfb = vf + (size_t)bv*CCH*NPIX;
    for (int kt=0; kt<4; kt++){
        __syncthreads();
        for (int idx=t; idx<96*64; idx+=256) w1s[idx]=w1[kt*96*64+idx];
        __syncthreads();
        #pragma unroll 2
        for (int c=0;c<96;c++){
            float v = vfb[(kt*96+c)*NPIX + pix];
            u64 vp = pk2(v,v);
            const ulonglong2* wr = (const ulonglong2*)(w1s + c*64 + og);
            #pragma unroll
            for (int q=0;q<4;q++){
                ulonglong2 w = wr[q];
                acc[2*q]   = fma2_(vp, w.x, acc[2*q]);
                acc[2*q+1] = fma2_(vp, w.y, acc[2*q+1]);
            }
        }
    }
    ulonglong2* dst = (ulonglong2*)(g_proj + ((size_t)bv*NPIX + pix)*64 + og);
    #pragma unroll
    for (int q=0;q<4;q++){
        ulonglong2 o; o.x=acc[2*q]; o.y=acc[2*q+1];
        dst[q]=o;
    }
}

// ---------------------------------------------------------------------------
// Kernel B: per-point fusion -> g_fused (B,N,32). One point per thread.
// Warp-cooperative gather; register blend; single STS.128 per (point,chunk).
// Fast-erf GELU; packed-f32x2 LN epilogue. (Unchanged from R13 best.)
// ---------------------------------------------------------------------------
__global__ void __launch_bounds__(128) pointK(
    const float* __restrict__ xyz, const float* __restrict__ g14,
    const float* __restrict__ extp, const float* __restrict__ intrp,
    const float* __restrict__ off, const int* __restrict__ mask,
    const float* __restrict__ b1, const float* __restrict__ w2,
    const float* __restrict__ b2, const float* __restrict__ lnw,
    const float* __restrict__ lnb,
    const float* __restrict__ gw1, const float* __restrict__ gb1,
    const float* __restrict__ gw2, const float* __restrict__ gb2)
{
    __shared__ __align__(16) float s_h[4*32*68];
    __shared__ __align__(16) float s_w2[64*32];
    __shared__ __align__(16) float s_b1[64];
    __shared__ __align__(16) float s_b2[32];
    __shared__ __align__(16) float s_lnw[32];
    __shared__ __align__(16) float s_lnb[32];
    __shared__ float s_ext[NVIEW*12], s_intr[NVIEW*9];
    __shared__ float s_gw1[64], s_gb1[16], s_gw2[16];
    __shared__ float s_gb2;
    __shared__ uint2 s_pix[128];
    __shared__ __align__(16) float s_wt[128*4];
    int t = threadIdx.x;
    int b = blockIdx.y;
    int n = blockIdx.x*128 + t;
    int lane = t & 31;
    int wid  = t >> 5;
    int half16 = (lane >> 4) << 4;
    int qc = lane & 15;
    for (int i=t;i<2048;i+=128) s_w2[i]=w2[i];
    if (t<64){ s_b1[t]=b1[t]; s_gw1[t]=gw1[t]; }
    if (t<32){ s_b2[t]=b2[t]; s_lnw[t]=lnw[t]; s_lnb[t]=lnb[t]; }
    if (t<16){ s_gb1[t]=gb1[t]; s_gw2[t]=gw2[t]; }
    if (t<NVIEW*12) s_ext[t]=extp[b*NVIEW*12+t];
    if (t<NVIEW*9)  s_intr[t]=intrp[b*NVIEW*9+t];
    if (t==0) s_gb2=gb2[0];
    __syncthreads();

    size_t pt = (size_t)b*NPTS + n;
    float px = xyz[pt*3+0], py = xyz[pt*3+1], pz = xyz[pt*3+2];
    const float* g = g14 + pt*14;
    float sc0 = fminf(fmaxf(g[4],0.01f),10.f);
    float sc1 = fminf(fmaxf(g[5],0.01f),10.f);
    float sc2 = fminf(fmaxf(g[6],0.01f),10.f);
    float opc = fminf(fmaxf(g[11],0.f),1.f);
    float gacc = s_gb2;
    #pragma unroll
    for (int h=0;h<16;h++){
        float z = s_gb1[h] + sc0*s_gw1[h] + sc1*s_gw1[16+h]
                + sc2*s_gw1[32+h] + opc*s_gw1[48+h];
        gacc += geluf(z)*s_gw2[h];
    }
    float gate = sigmoidf_(gacc);
    float offx = off[pt*2+0], offy = off[pt*2+1];
    bool  mk   = (mask[pt] != 0);

    u64 sumf[16];
    #pragma unroll
    for (int j=0;j<16;j++) sumf[j]=0ull;
    float summ = 0.f;
    float* hwarp = s_h + wid*(32*68);
    float* hrow  = hwarp + lane*68;
    const u64* b2p  = (const u64*)s_b2;
    const u64* lnwp = (const u64*)s_lnw;
    const u64* lnbp = (const u64*)s_lnb;

    for (int v=0; v<NVIEW; v++){
        const float* E  = s_ext  + v*12;
        const float* Km = s_intr + v*9;
        float cx = E[0]*px+E[1]*py+E[2]*pz+E[3];
        float cy = E[4]*px+E[5]*py+E[6]*pz+E[7];
        float cz = E[8]*px+E[9]*py+E[10]*pz+E[11];
        float ux = Km[0]*cx+Km[1]*cy+Km[2]*cz;
        float uy = Km[3]*cx+Km[4]*cy+Km[5]*cz;
        float uz = Km[6]*cx+Km[7]*cy+Km[8]*cz;
        float depth = fmaxf(uz, 1e-6f);
        float gx = 2.f*(ux/depth)/448.f - 1.f + offx;
        float gy = 2.f*(uy/depth)/448.f - 1.f + offy;
        bool valid = (uz>0.1f) && (fabsf(gx)<=1.f) && (fabsf(gy)<=1.f) && mk;
        float vm = valid ? 1.f : 0.f;
        float xs = fminf(fmaxf(((gx+1.f)*32.f - 1.f)*0.5f, -100.f), 100.f);
        float ys = fminf(fmaxf(((gy+1.f)*32.f - 1.f)*0.5f, -100.f), 100.f);
        float x0f = floorf(xs), y0f = floorf(ys);
        float wx = xs-x0f, wy = ys-y0f;
        int x0=(int)x0f, y0=(int)y0f;
        unsigned int xc0 = (unsigned)min(max(x0  ,0),31);
        unsigned int xc1 = (unsigned)min(max(x0+1,0),31);
        unsigned int yc0 = (unsigned)min(max(y0  ,0),31);
        unsigned int yc1 = (unsigned)min(max(y0+1,0),31);
        bool vx0 = (x0>=0)&&(x0<32),  vx1 = (x0+1>=0)&&(x0+1<32);
        bool vy0 = (y0>=0)&&(y0<32),  vy1 = (y0+1>=0)&&(y0+1<32);
        float w00 = (1.f-wx)*(1.f-wy)*((vx0&&vy0)?vm:0.f);
        float w10 = wx*(1.f-wy)      *((vx1&&vy0)?vm:0.f);
        float w01 = (1.f-wx)*wy      *((vx0&&vy1)?vm:0.f);
        float w11 = wx*wy            *((vx1&&vy1)?vm:0.f);
        s_pix[t] = make_uint2((yc0*32+xc0) | ((yc0*32+xc1)<<16),
                              (yc1*32+xc0) | ((yc1*32+xc1)<<16));
        s_wt[t*4+0]=w00; s_wt[t*4+1]=w10; s_wt[t*4+2]=w01; s_wt[t*4+3]=w11;
        __syncwarp();

        const float* pb = g_proj + (size_t)(b*NVIEW+v)*NPIX*64;
        int wbase = wid*32;
        #pragma unroll 4
        for (int s16=0; s16<16; s16++){
            int srcp = s16 + half16;
            int sidx = wbase + srcp;
            uint2 pp = s_pix[sidx];
            float4 wt = *(const float4*)(s_wt + sidx*4);
            ulonglong2 v00 = *((const ulonglong2*)(pb + (size_t)(pp.x&0xffffu)*64) + qc);
            ulonglong2 v10 = *((const ulonglong2*)(pb + (size_t)(pp.x>>16)*64) + qc);
            ulonglong2 v01 = *((const ulonglong2*)(pb + (size_t)(pp.y&0xffffu)*64) + qc);
            ulonglong2 v11 = *((const ulonglong2*)(pb + (size_t)(pp.y>>16)*64) + qc);
            u64 w00p=pk2(wt.x,wt.x), w10p=pk2(wt.y,wt.y);
            u64 w01p=pk2(wt.z,wt.z), w11p=pk2(wt.w,wt.w);
            ulonglong2 o;
            o.x = fma2_(w11p,v11.x, fma2_(w01p,v01.x, fma2_(w10p,v10.x, mul2_(w00p,v00.x))));
            o.y = fma2_(w11p,v11.y, fma2_(w01p,v01.y, fma2_(w10p,v10.y, mul2_(w00p,v00.y))));
            *(ulonglong2*)(hwarp + srcp*68 + qc*4) = o;
        }
        __syncwarp();

        u64 yp[16];
        #pragma unroll
        for (int i=0;i<16;i++) yp[i]=b2p[i];
        #pragma unroll 2
        for (int c=0;c<16;c++){
            float4 hv = *(float4*)(hrow + c*4);
            float h0=geluf(hv.x + s_b1[4*c+0]);
            float h1=geluf(hv.y + s_b1[4*c+1]);
            float h2=geluf(hv.z + s_b1[4*c+2]);
            float h3=geluf(hv.w + s_b1[4*c+3]);
            u64 h0p=pk2(h0,h0), h1p=pk2(h1,h1), h2p=pk2(h2,h2), h3p=pk2(h3,h3);
            const ulonglong2* r0=(const ulonglong2*)(s_w2+(4*c  )*32);
            const ulonglong2* r1=(const ulonglong2*)(s_w2+(4*c+1)*32);
            const ulonglong2* r2=(const ulonglong2*)(s_w2+(4*c+2)*32);
            const ulonglong2* r3=(const ulonglong2*)(s_w2+(4*c+3)*32);
            #pragma unroll
            for (int q=0;q<8;q++){
                ulonglong2 w0=r0[q],w1=r1[q],w2v=r2[q],w3=r3[q];
                yp[2*q]   = fma2_(h0p,w0.x,fma2_(h1p,w1.x,fma2_(h2p,w2v.x,fma2_(h3p,w3.x,yp[2*q]))));
                yp[2*q+1] = fma2_(h0p,w0.y,fma2_(h1p,w1.y,fma2_(h2p,w2v.y,fma2_(h3p,w3.y,yp[2*q+1]))));
            }
        }
        u64 t8[8];
        #pragma unroll
        for (int i=0;i<8;i++) t8[i]=add2_(yp[2*i],yp[2*i+1]);
        u64 t4a=add2_(t8[0],t8[1]), t4b=add2_(t8[2],t8[3]);
        u64 t4c=add2_(t8[4],t8[5]), t4d=add2_(t8[6],t8[7]);
        u64 t2a=add2_(t4a,t4b),     t2b=add2_(t4c,t4d);
        u64 tt = add2_(t2a,t2b);
        float slo,shi; up2(tt,slo,shi);
        float m = (slo+shi)*(1.f/32.f);
        u64 mn = pk2(-m,-m);
        u64 vacc = 0ull;
        #pragma unroll
        for (int i=0;i<16;i++){
            u64 d = add2_(yp[i], mn);
            vacc = fma2_(d,d,vacc);
        }
        float vlo,vhi; up2(vacc,vlo,vhi);
        float var = (vlo+vhi)*(1.f/32.f);
        float rinv = rsqrtf(var + 1e-5f);
        float gv = gate*vm;
        summ += vm;
        u64 rp = pk2(rinv,rinv), gp = pk2(gv,gv);
        #pragma unroll
        for (int i=0;i<16;i++){
            u64 t1 = add2_(yp[i], mn);
            u64 t2 = mul2_(t1, rp);
            u64 t3 = fma2_(t2, lnwp[i], lnbp[i]);
            sumf[i] = fma2_(t3, gp, sumf[i]);
        }
    }
    float fin = 1.f/(summ + 1e-6f);
    float4* fo = (float4*)(g_fused + pt*32);
    #pragma unroll
    for (int q=0;q<8;q++){
        float a0,a1,a2,a3;
        up2(sumf[2*q],   a0, a1);
        up2(sumf[2*q+1], a2, a3);
        fo[q] = make_float4(a0*fin, a1*fin, a2*fin, a3*fin);
    }
}

// ---------------------------------------------------------------------------
// Kernel B2: act = softmax(LN(fused @ cw)) * mask  -> g_act (B,N,64)
// 2 threads per point (32 outputs each); LN/softmax stats combined via
// shfl_xor(1). Halves regs & per-thread FLOPs vs R13.
// ---------------------------------------------------------------------------
__global__ void __launch_bounds__(128) actK(const float* __restrict__ cw,
    const float* __restrict__ l1w, const float* __restrict__ l1b,
    const int* __restrict__ mask)
{
    __shared__ __align__(16) float scw[2048];
    __shared__ float swn[64], sbn[64];
    int t = threadIdx.x;
    for (int i=t;i<2048;i+=128) scw[i]=cw[i];
    if (t<64){ swn[t]=l1w[t]; sbn[t]=l1b[t]; }
    __syncthreads();
    int half = t & 1;
    size_t pt = (size_t)blockIdx.x*64 + (t >> 1);
    float fv[32];
    const float4* fp = (const float4*)(g_fused + pt*32);
    #pragma unroll
    for (int q=0;q<8;q++){
        float4 f=fp[q];
        fv[4*q]=f.x; fv[4*q+1]=f.y; fv[4*q+2]=f.z; fv[4*q+3]=f.w;
    }
    u64 acc[16];
    #pragma unroll
    for (int i=0;i<16;i++) acc[i]=0ull;
    #pragma unroll
    for (int j=0;j<32;j++){
        u64 fjp = pk2(fv[j],fv[j]);
        const ulonglong2* cr = (const ulonglong2*)(scw + j*64 + half*32);
        #pragma unroll
        for (int q=0;q<8;q++){
            ulonglong2 w=cr[q];
            acc[2*q]   = fma2_(fjp, w.x, acc[2*q]);
            acc[2*q+1] = fma2_(fjp, w.y, acc[2*q+1]);
        }
    }
    float row[32];
    #pragma unroll
    for (int i=0;i<16;i++) up2(acc[i], row[2*i], row[2*i+1]);
    // mean over full 64 (pairwise via shfl with partner t^1)
    float s=0.f;
    #pragma unroll
    for (int k=0;k<32;k++) s+=row[k];
    s += __shfl_xor_sync(0xffffffffu, s, 1);
    float m = s*(1.f/64.f);
    float vv=0.f;
    #pragma unroll
    for (int k=0;k<32;k++){ float d=row[k]-m; vv+=d*d; }
    vv += __shfl_xor_sync(0xffffffffu, vv, 1);
    float rinv = rsqrtf(vv*(1.f/64.f)+1e-5f);
    float mx=-1e30f;
    #pragma unroll
    for (int k=0;k<32;k++){
        float val=(row[k]-m)*rinv*swn[half*32+k]+sbn[half*32+k];
        row[k]=val;
        mx=fmaxf(mx,val);
    }
    mx = fmaxf(mx, __shfl_xor_sync(0xffffffffu, mx, 1));
    float sum=0.f;
    #pragma unroll
    for (int k=0;k<32;k++){
        float e=__expf(row[k]-mx);
        row[k]=e; sum+=e;
    }
    sum += __shfl_xor_sync(0xffffffffu, sum, 1);
    float mkf = (mask[pt]!=0) ? 1.f : 0.f;
    float scl = mkf/sum;
    float4* ap = (float4*)(g_act + pt*64 + half*32);
    #pragma unroll
    for (int q=0;q<8;q++)
        ap[q] = make_float4(row[4*q]*scl,row[4*q+1]*scl,row[4*q+2]*scl,row[4*q+3]*scl);
}

// ---------------------------------------------------------------------------
// Kernel C: split-K partials of vlad[b][d][k] = sum_n fused[n][d]*act[n][k]
// ---------------------------------------------------------------------------
__global__ void __launch_bounds__(256) vladK(){
    int b = blockIdx.y, chunk = blockIdx.x, t = threadIdx.x;
    __shared__ __align__(16) float fs[64*32];
    __shared__ __align__(16) float as_[64*64];
    __shared__ float sasum[256];
    int k0 = (t & 15) * 4;
    int d0 = (t >> 4) * 2;
    float acc[2][4];
    #pragma unroll
    for (int i=0;i<2;i++)
        #pragma unroll
        for (int j=0;j<4;j++) acc[i][j]=0.f;
    float asum = 0.f;
    int pa_off = t >> 6;
    int pa_col = t & 63;
    const float* fbase = g_fused + ((size_t)b*NPTS + (size_t)chunk*CHPTS)*32;
    const float* abase = g_act   + ((size_t)b*NPTS + (size_t)chunk*CHPTS)*64;

    for (int tile=0; tile<CHPTS/64; tile++){
        __syncthreads();
        {
            const float4* fsrc = (const float4*)(fbase + tile*64*32);
            const float4* asrc = (const float4*)(abase + tile*64*64);
            float4* fdst = (float4*)fs;
            float4* adst = (float4*)as_;
            #pragma unroll
            for (int i=0;i<2;i++) fdst[t + 256*i] = fsrc[t + 256*i];
            #pragma unroll
            for (int i=0;i<4;i++) adst[t + 256*i] = asrc[t + 256*i];
        }
        __syncthreads();
        #pragma unroll 4
        for (int p=0;p<64;p++){
            float2 f = *(const float2*)(fs  + p*32 + d0);
            float4 a = *(const float4*)(as_ + p*64 + k0);
            acc[0][0] += f.x*a.x; acc[0][1] += f.x*a.y;
            acc[0][2] += f.x*a.z; acc[0][3] += f.x*a.w;
            acc[1][0] += f.y*a.x; acc[1][1] += f.y*a.y;
            acc[1][2] += f.y*a.z; acc[1][3] += f.y*a.w;
        }
        #pragma unroll
        for (int i=0;i<16;i++)
            asum += as_[(pa_off + 4*i)*64 + pa_col];
    }
    float* pv = g_pv + ((size_t)b*NCHUNK+chunk)*2048;
    *(float4*)(pv + (d0  )*64 + k0) = make_float4(acc[0][0],acc[0][1],acc[0][2],acc[0][3]);
    *(float4*)(pv + (d0+1)*64 + k0) = make_float4(acc[1][0],acc[1][1],acc[1][2],acc[1][3]);
    sasum[t] = asum;
    __syncthreads();
    if (t<64)
        g_pa[((size_t)b*NCHUNK+chunk)*64+t] =
            sasum[t] + sasum[64+t] + sasum[128+t] + sasum[192+t];
}

// ---------------------------------------------------------------------------
// Kernel C2: reduce g_pv over chunks -> g_vl (B,2048).
// ---------------------------------------------------------------------------
__global__ void __launch_bounds__(256) redK(){
    __shared__ float red[256];
    int b = blockIdx.y;
    int cell0 = blockIdx.x * 16;
    int t = threadIdx.x;
    int ci = t & 15;
    int cg = t >> 4;
    const float* src = g_pv + (size_t)b*NCHUNK*2048 + cell0 + ci;
    float s = 0.f;
    #pragma unroll
    for (int c=0;c<8;c++) s += src[(size_t)(cg*8+c)*2048];
    red[t]=s; __syncthreads();
    #pragma unroll
    for (int o=128;o>=16;o>>=1){
        if (t<o) red[t]+=red[t+o];
        __syncthreads();
    }
    if (t<16) g_vl[b*2048 + cell0 + t] = red[t];
}

// ---------------------------------------------------------------------------
// Kernel D1: per-batch normalize. grid (B), 256 threads.
// ---------------------------------------------------------------------------
__global__ void __launch_bounds__(256) normK(const float* __restrict__ cw2){
    int b = blockIdx.x, t = threadIdx.x;
    __shared__ float vl[2048];
    __shared__ float asums[64];
    __shared__ float red[256];
    __shared__ float scs;
    if (t<64){
        float a=0.f;
        #pragma unroll 8
        for (int c=0;c<NCHUNK;c++) a += g_pa[((size_t)b*NCHUNK+c)*64+t];
        asums[t]=a;
    }
    __syncthreads();
    #pragma unroll
    for (int s=0;s<8;s++){
        int cell=t+256*s;
        vl[cell] = g_vl[b*2048+cell] - asums[cell&63]*cw2[cell];
    }
    __syncthreads();
    if (t<64){
        float nsq=0.f;
        for (int d=0; d<32; d++){ float v=vl[d*64+t]; nsq += v*v; }
        asums[t] = 1.f/fmaxf(sqrtf(nsq), 1e-12f);
    }
    __syncthreads();
    float lsq=0.f;
    #pragma unroll
    for (int s=0;s<8;s++){
        int cell=t+256*s;
        float v = vl[cell]*asums[cell&63];
        vl[cell]=v; lsq += v*v;
    }
    red[t]=lsq; __syncthreads();
    for (int o=128;o>0;o>>=1){ if (t<o) red[t]+=red[t+o]; __syncthreads(); }
    if (t==0) scs = 1.f/fmaxf(sqrtf(red[0]),1e-12f);
    __syncthreads();
    float scale = scs;
    #pragma unroll
    for (int s=0;s<8;s++)
        g_vl[b*2048 + t+256*s] = vl[t+256*s]*scale;
}

// ---------------------------------------------------------------------------
// Kernel D2: out = vlad @ hw (2048 -> 256). grid (8, B), 256 thr.
// ---------------------------------------------------------------------------
__global__ void __launch_bounds__(256) outK(const float* __restrict__ hw){
    int b = blockIdx.y, c0 = blockIdx.x*32, t = threadIdx.x;
    int col = t & 31, seg = t >> 5;
    __shared__ float vls[2048];
    __shared__ float red[256];
    for (int i=t;i<2048;i+=256) vls[i]=g_vl[b*2048+i];
    __syncthreads();
    float s=0.f;
    const float* hp = hw + c0 + col;
    int i0 = seg*256;
    #pragma unroll 4
    for (int i=i0;i<i0+256;i++) s += vls[i]*hp[(size_t)i*256];
    red[t]=s; __syncthreads();
    if (t<32){
        float o=0.f;
        #pragma unroll
        for (int g2=0; g2<8; g2++) o += red[g2*32+t];
        g_out[b*256+c0+t]=o;
    }
}

// ---------------------------------------------------------------------------
// Kernel D3: gates = sigmoid(LN(out @ gw)); outp = out * gates. grid (B).
// ---------------------------------------------------------------------------
__global__ void __launch_bounds__(256) gateK(const float* __restrict__ gw,
    const float* __restrict__ glnw, const float* __restrict__ glnb,
    float* __restrict__ outp)
{
    int b = blockIdx.x, t = threadIdx.x;
    __shared__ float outs[256];
    __shared__ float red[256];
    outs[t]=g_out[b*256+t]; __syncthreads();
    float ov = outs[t];
    float gv=0.f;
    #pragma unroll 4
    for (int i=0;i<256;i++) gv += outs[i]*gw[i*256+t];
    red[t]=gv; __syncthreads();
    for (int o=128;o>0;o>>=1){ if (t<o) red[t]+=red[t+o]; __syncthreads(); }
    float m = red[0]*(1.f/256.f);
    __syncthreads();
    float dv = gv-m;
    red[t]=dv*dv; __syncthreads();
    for (int o=128;o>0;o>>=1){ if (t<o) red[t]+=red[t+o]; __syncthreads(); }
    float var = red[0]*(1.f/256.f);
    float gn = (gv-m)*rsqrtf(var+1e-5f)*glnw[t]+glnb[t];
    outp[b*256+t] = ov * sigmoidf_(gn);
}

// ---------------------------------------------------------------------------
// launch
// ---------------------------------------------------------------------------
extern "C" void kernel_launch(void* const* d_in, const int* in_sizes, int n_in,
                              void* d_out, int out_size)
{
    const float* xyz   = (const float*)d_in[0];
    const float* g14d  = (const float*)d_in[1];
    const float* vfeat = (const float*)d_in[2];
    const float* ext   = (const float*)d_in[3];
    const float* intr  = (const float*)d_in[4];
    const float* offs  = (const float*)d_in[5];
    const int*   mask  = (const int*)d_in[6];
    const float* gate_w1 = (const float*)d_in[7];
    const float* gate_b1 = (const float*)d_in[8];
    const float* gate_w2 = (const float*)d_in[9];
    const float* gate_b2 = (const float*)d_in[10];
    const float* bn_w1   = (const float*)d_in[11];
    const float* bn_b1   = (const float*)d_in[12];
    const float* bn_w2   = (const float*)d_in[13];
    const float* bn_b2   = (const float*)d_in[14];
    const float* bn_ln_w = (const float*)d_in[15];
    const float* bn_ln_b = (const float*)d_in[16];
    const float* cw      = (const float*)d_in[17];
    const float* cw2     = (const float*)d_in[18];
    const float* hw      = (const float*)d_in[19];
    const float* ln1_w   = (const float*)d_in[20];
    const float* ln1_b   = (const float*)d_in[21];
    const float* gw      = (const float*)d_in[22];
    const float* gln_w   = (const float*)d_in[23];
    const float* gln_b   = (const float*)d_in[24];
    float* out = (float*)d_out;

    projK<<<dim3(BATCH*NVIEW, NPIX/64), 256>>>(vfeat, bn_w1);
    pointK<<<dim3(NPTS/128, BATCH), 128>>>(xyz, g14d, ext, intr, offs, mask,
        bn_b1, bn_w2, bn_b2, bn_ln_w, bn_ln_b,
        gate_w1, gate_b1, gate_w2, gate_b2);
    actK<<<dim3((BATCH*NPTS)/64), 128>>>(cw, ln1_w, ln1_b, mask);
    vladK<<<dim3(NCHUNK, BATCH), 256>>>();
    redK<<<dim3(128, BATCH), 256>>>();
    normK<<<BATCH, 256>>>(cw2);
    outK<<<dim3(8, BATCH), 256>>>(hw);
    gateK<<<BATCH, 256>>>(gw, gln_w, gln_b, out);
}

// round 15
// speedup vs baseline: 1.0149x; 1.0149x over previous
#include <cuda_runtime.h>
#include <cuda_bf16.h>
#include <math.h>

#define BATCH 4
#define NPTS 16384
#define NVIEW 6
#define CCH 384
#define HH 32
#define WW 32
#define NPIX (HH*WW)
#define NCHUNK 128
#define CHPTS (NPTS/NCHUNK)   // 128

typedef unsigned long long u64;

// scratch (static device globals; no allocation anywhere)
__device__ __align__(16) float g_proj [BATCH*NVIEW*NPIX*64];   // 6.3 MB
__device__ __align__(16) float g_fused[BATCH*NPTS*32];         // 8 MB
__device__ __align__(16) float g_act  [BATCH*NPTS*64];         // 16 MB
__device__ __align__(16) float g_pv   [BATCH*NCHUNK*2048];     // 4 MB
__device__ __align__(16) float g_pa   [BATCH*NCHUNK*64];
__device__ __align__(16) float g_vl   [BATCH*2048];
__device__ __align__(16) float g_out  [BATCH*256];

// Branchless erf-based GELU: A&S 7.1.26 (max abs err ~1.5e-7), MUFU-backed.
__device__ __forceinline__ float geluf(float x){
    float xe = x*0.70710678118654752f;
    float ax = fabsf(xe);
    float t  = __fdividef(1.f, fmaf(0.3275911f, ax, 1.f));
    float p  = t*fmaf(t, fmaf(t, fmaf(t, fmaf(t, 1.061405429f, -1.453152027f),
                 1.421413741f), -0.284496736f), 0.254829592f);
    float e  = __expf(-ax*ax);
    float er = fmaf(-p, e, 1.f);
    er = copysignf(er, xe);
    return 0.5f*x*(1.f+er);
}
__device__ __forceinline__ float sigmoidf_(float x){
    return 1.f/(1.f+expf(-x));
}
// ---- packed f32x2 helpers (Blackwell; ptxas won't emit from C++) ----
__device__ __forceinline__ u64 pk2(float lo, float hi){
    u64 r; asm("mov.b64 %0,{%1,%2};" : "=l"(r) : "f"(lo), "f"(hi)); return r;
}
__device__ __forceinline__ void up2(u64 v, float& lo, float& hi){
    asm("mov.b64 {%0,%1},%2;" : "=f"(lo), "=f"(hi) : "l"(v));
}
__device__ __forceinline__ u64 fma2_(u64 a, u64 b, u64 c){
    u64 d; asm("fma.rn.f32x2 %0,%1,%2,%3;" : "=l"(d) : "l"(a), "l"(b), "l"(c)); return d;
}
__device__ __forceinline__ u64 mul2_(u64 a, u64 b){
    u64 d; asm("mul.rn.f32x2 %0,%1,%2;" : "=l"(d) : "l"(a), "l"(b)); return d;
}
__device__ __forceinline__ u64 add2_(u64 a, u64 b){
    u64 d; asm("add.rn.f32x2 %0,%1,%2;" : "=l"(d) : "l"(a), "l"(b)); return d;
}

// ---------------------------------------------------------------------------
// Kernel A: proj[bv][pix][o] = sum_c vf[bv][c][pix] * w1[c][o]
// (R13 layout: grid (24,8), 128 pix, 2 output halves per 256-thread block.)
// ---------------------------------------------------------------------------
__global__ void __launch_bounds__(256) projK(const float* __restrict__ vf,
                                             const float* __restrict__ w1){
    __shared__ __align__(16) float w1s[96*64];
    int t = threadIdx.x;
    int bv  = blockIdx.x;
    int half = t >> 7;
    int pix = blockIdx.y*128 + (t & 127);
    int og  = half*32;
    u64 acc[16];
    #pragma unroll
    for (int i=0;i<16;i++) acc[i]=0ull;
    const float* vfb = vf + (size_t)bv*CCH*NPIX;
    for (int kt=0; kt<4; kt++){
        __syncthreads();
        for (int idx=t; idx<96*64; idx+=256) w1s[idx]=w1[kt*96*64+idx];
        __syncthreads();
        #pragma unroll 2
        for (int c=0;c<96;c++){
            float v = vfb[(kt*96+c)*NPIX + pix];
            u64 vp = pk2(v,v);
            const ulonglong2* wr = (const ulonglong2*)(w1s + c*64 + og);
            #pragma unroll
            for (int q=0;q<8;q++){
                ulonglong2 w = wr[q];
                acc[2*q]   = fma2_(vp, w.x, acc[2*q]);
                acc[2*q+1] = fma2_(vp, w.y, acc[2*q+1]);
            }
        }
    }
    ulonglong2* dst = (ulonglong2*)(g_proj + ((size_t)bv*NPIX + pix)*64 + og);
    #pragma unroll
    for (int q=0;q<8;q++){
        ulonglong2 o; o.x=acc[2*q]; o.y=acc[2*q+1];
        dst[q]=o;
    }
}

// ---------------------------------------------------------------------------
// Kernel B: per-point fusion -> g_fused (B,N,32). (Unchanged from R13 best.)
// ---------------------------------------------------------------------------
__global__ void __launch_bounds__(128) pointK(
    const float* __restrict__ xyz, const float* __restrict__ g14,
    const float* __restrict__ extp, const float* __restrict__ intrp,
    const float* __restrict__ off, const int* __restrict__ mask,
    const float* __restrict__ b1, const float* __restrict__ w2,
    const float* __restrict__ b2, const float* __restrict__ lnw,
    const float* __restrict__ lnb,
    const float* __restrict__ gw1, const float* __restrict__ gb1,
    const float* __restrict__ gw2, const float* __restrict__ gb2)
{
    __shared__ __align__(16) float s_h[4*32*68];
    __shared__ __align__(16) float s_w2[64*32];
    __shared__ __align__(16) float s_b1[64];
    __shared__ __align__(16) float s_b2[32];
    __shared__ __align__(16) float s_lnw[32];
    __shared__ __align__(16) float s_lnb[32];
    __shared__ float s_ext[NVIEW*12], s_intr[NVIEW*9];
    __shared__ float s_gw1[64], s_gb1[16], s_gw2[16];
    __shared__ float s_gb2;
    __shared__ uint2 s_pix[128];
    __shared__ __align__(16) float s_wt[128*4];
    int t = threadIdx.x;
    int b = blockIdx.y;
    int n = blockIdx.x*128 + t;
    int lane = t & 31;
    int wid  = t >> 5;
    int half16 = (lane >> 4) << 4;
    int qc = lane & 15;
    for (int i=t;i<2048;i+=128) s_w2[i]=w2[i];
    if (t<64){ s_b1[t]=b1[t]; s_gw1[t]=gw1[t]; }
    if (t<32){ s_b2[t]=b2[t]; s_lnw[t]=lnw[t]; s_lnb[t]=lnb[t]; }
    if (t<16){ s_gb1[t]=gb1[t]; s_gw2[t]=gw2[t]; }
    if (t<NVIEW*12) s_ext[t]=extp[b*NVIEW*12+t];
    if (t<NVIEW*9)  s_intr[t]=intrp[b*NVIEW*9+t];
    if (t==0) s_gb2=gb2[0];
    __syncthreads();

    size_t pt = (size_t)b*NPTS + n;
    float px = xyz[pt*3+0], py = xyz[pt*3+1], pz = xyz[pt*3+2];
    const float* g = g14 + pt*14;
    float sc0 = fminf(fmaxf(g[4],0.01f),10.f);
    float sc1 = fminf(fmaxf(g[5],0.01f),10.f);
    float sc2 = fminf(fmaxf(g[6],0.01f),10.f);
    float opc = fminf(fmaxf(g[11],0.f),1.f);
    float gacc = s_gb2;
    #pragma unroll
    for (int h=0;h<16;h++){
        float z = s_gb1[h] + sc0*s_gw1[h] + sc1*s_gw1[16+h]
                + sc2*s_gw1[32+h] + opc*s_gw1[48+h];
        gacc += geluf(z)*s_gw2[h];
    }
    float gate = sigmoidf_(gacc);
    float offx = off[pt*2+0], offy = off[pt*2+1];
    bool  mk   = (mask[pt] != 0);

    u64 sumf[16];
    #pragma unroll
    for (int j=0;j<16;j++) sumf[j]=0ull;
    float summ = 0.f;
    float* hwarp = s_h + wid*(32*68);
    float* hrow  = hwarp + lane*68;
    const u64* b2p  = (const u64*)s_b2;
    const u64* lnwp = (const u64*)s_lnw;
    const u64* lnbp = (const u64*)s_lnb;

    for (int v=0; v<NVIEW; v++){
        const float* E  = s_ext  + v*12;
        const float* Km = s_intr + v*9;
        float cx = E[0]*px+E[1]*py+E[2]*pz+E[3];
        float cy = E[4]*px+E[5]*py+E[6]*pz+E[7];
        float cz = E[8]*px+E[9]*py+E[10]*pz+E[11];
        float ux = Km[0]*cx+Km[1]*cy+Km[2]*cz;
        float uy = Km[3]*cx+Km[4]*cy+Km[5]*cz;
        float uz = Km[6]*cx+Km[7]*cy+Km[8]*cz;
        float depth = fmaxf(uz, 1e-6f);
        float gx = 2.f*(ux/depth)/448.f - 1.f + offx;
        float gy = 2.f*(uy/depth)/448.f - 1.f + offy;
        bool valid = (uz>0.1f) && (fabsf(gx)<=1.f) && (fabsf(gy)<=1.f) && mk;
        float vm = valid ? 1.f : 0.f;
        float xs = fminf(fmaxf(((gx+1.f)*32.f - 1.f)*0.5f, -100.f), 100.f);
        float ys = fminf(fmaxf(((gy+1.f)*32.f - 1.f)*0.5f, -100.f), 100.f);
        float x0f = floorf(xs), y0f = floorf(ys);
        float wx = xs-x0f, wy = ys-y0f;
        int x0=(int)x0f, y0=(int)y0f;
        unsigned int xc0 = (unsigned)min(max(x0  ,0),31);
        unsigned int xc1 = (unsigned)min(max(x0+1,0),31);
        unsigned int yc0 = (unsigned)min(max(y0  ,0),31);
        unsigned int yc1 = (unsigned)min(max(y0+1,0),31);
        bool vx0 = (x0>=0)&&(x0<32),  vx1 = (x0+1>=0)&&(x0+1<32);
        bool vy0 = (y0>=0)&&(y0<32),  vy1 = (y0+1>=0)&&(y0+1<32);
        float w00 = (1.f-wx)*(1.f-wy)*((vx0&&vy0)?vm:0.f);
        float w10 = wx*(1.f-wy)      *((vx1&&vy0)?vm:0.f);
        float w01 = (1.f-wx)*wy      *((vx0&&vy1)?vm:0.f);
        float w11 = wx*wy            *((vx1&&vy1)?vm:0.f);
        s_pix[t] = make_uint2((yc0*32+xc0) | ((yc0*32+xc1)<<16),
                              (yc1*32+xc0) | ((yc1*32+xc1)<<16));
        s_wt[t*4+0]=w00; s_wt[t*4+1]=w10; s_wt[t*4+2]=w01; s_wt[t*4+3]=w11;
        __syncwarp();

        const float* pb = g_proj + (size_t)(b*NVIEW+v)*NPIX*64;
        int wbase = wid*32;
        #pragma unroll 4
        for (int s16=0; s16<16; s16++){
            int srcp = s16 + half16;
            int sidx = wbase + srcp;
            uint2 pp = s_pix[sidx];
            float4 wt = *(const float4*)(s_wt + sidx*4);
            ulonglong2 v00 = *((const ulonglong2*)(pb + (size_t)(pp.x&0xffffu)*64) + qc);
            ulonglong2 v10 = *((const ulonglong2*)(pb + (size_t)(pp.x>>16)*64) + qc);
            ulonglong2 v01 = *((const ulonglong2*)(pb + (size_t)(pp.y&0xffffu)*64) + qc);
            ulonglong2 v11 = *((const ulonglong2*)(pb + (size_t)(pp.y>>16)*64) + qc);
            u64 w00p=pk2(wt.x,wt.x), w10p=pk2(wt.y,wt.y);
            u64 w01p=pk2(wt.z,wt.z), w11p=pk2(wt.w,wt.w);
            ulonglong2 o;
            o.x = fma2_(w11p,v11.x, fma2_(w01p,v01.x, fma2_(w10p,v10.x, mul2_(w00p,v00.x))));
            o.y = fma2_(w11p,v11.y, fma2_(w01p,v01.y, fma2_(w10p,v10.y, mul2_(w00p,v00.y))));
            *(ulonglong2*)(hwarp + srcp*68 + qc*4) = o;
        }
        __syncwarp();

        u64 yp[16];
        #pragma unroll
        for (int i=0;i<16;i++) yp[i]=b2p[i];
        #pragma unroll 2
        for (int c=0;c<16;c++){
            float4 hv = *(float4*)(hrow + c*4);
            float h0=geluf(hv.x + s_b1[4*c+0]);
            float h1=geluf(hv.y + s_b1[4*c+1]);
            float h2=geluf(hv.z + s_b1[4*c+2]);
            float h3=geluf(hv.w + s_b1[4*c+3]);
            u64 h0p=pk2(h0,h0), h1p=pk2(h1,h1), h2p=pk2(h2,h2), h3p=pk2(h3,h3);
            const ulonglong2* r0=(const ulonglong2*)(s_w2+(4*c  )*32);
            const ulonglong2* r1=(const ulonglong2*)(s_w2+(4*c+1)*32);
            const ulonglong2* r2=(const ulonglong2*)(s_w2+(4*c+2)*32);
            const ulonglong2* r3=(const ulonglong2*)(s_w2+(4*c+3)*32);
            #pragma unroll
            for (int q=0;q<8;q++){
                ulonglong2 w0=r0[q],w1=r1[q],w2v=r2[q],w3=r3[q];
                yp[2*q]   = fma2_(h0p,w0.x,fma2_(h1p,w1.x,fma2_(h2p,w2v.x,fma2_(h3p,w3.x,yp[2*q]))));
                yp[2*q+1] = fma2_(h0p,w0.y,fma2_(h1p,w1.y,fma2_(h2p,w2v.y,fma2_(h3p,w3.y,yp[2*q+1]))));
            }
        }
        u64 t8[8];
        #pragma unroll
        for (int i=0;i<8;i++) t8[i]=add2_(yp[2*i],yp[2*i+1]);
        u64 t4a=add2_(t8[0],t8[1]), t4b=add2_(t8[2],t8[3]);
        u64 t4c=add2_(t8[4],t8[5]), t4d=add2_(t8[6],t8[7]);
        u64 t2a=add2_(t4a,t4b),     t2b=add2_(t4c,t4d);
        u64 tt = add2_(t2a,t2b);
        float slo,shi; up2(tt,slo,shi);
        float m = (slo+shi)*(1.f/32.f);
        u64 mn = pk2(-m,-m);
        u64 vacc = 0ull;
        #pragma unroll
        for (int i=0;i<16;i++){
            u64 d = add2_(yp[i], mn);
            vacc = fma2_(d,d,vacc);
        }
        float vlo,vhi; up2(vacc,vlo,vhi);
        float var = (vlo+vhi)*(1.f/32.f);
        float rinv = rsqrtf(var + 1e-5f);
        float gv = gate*vm;
        summ += vm;
        u64 rp = pk2(rinv,rinv), gp = pk2(gv,gv);
        #pragma unroll
        for (int i=0;i<16;i++){
            u64 t1 = add2_(yp[i], mn);
            u64 t2 = mul2_(t1, rp);
            u64 t3 = fma2_(t2, lnwp[i], lnbp[i]);
            sumf[i] = fma2_(t3, gp, sumf[i]);
        }
    }
    float fin = 1.f/(summ + 1e-6f);
    float4* fo = (float4*)(g_fused + pt*32);
    #pragma unroll
    for (int q=0;q<8;q++){
        float a0,a1,a2,a3;
        up2(sumf[2*q],   a0, a1);
        up2(sumf[2*q+1], a2, a3);
        fo[q] = make_float4(a0*fin, a1*fin, a2*fin, a3*fin);
    }
}

// ---------------------------------------------------------------------------
// Kernel B2: act = softmax(LN(fused @ cw)) * mask  -> g_act (B,N,64)
// LOW-REG version: fv staged in smem (stride-65 rows, conflict-free);
// matvec in two temporal 32-wide halves reusing one acc[16] (u64);
// lower half-row parked in smem, upper half kept packed in acc.
// Peak live regs ~50 -> high occupancy, zero spills.
// ---------------------------------------------------------------------------
__global__ void __launch_bounds__(128) actK(const float* __restrict__ cw,
    const float* __restrict__ l1w, const float* __restrict__ l1b,
    const int* __restrict__ mask)
{
    __shared__ __align__(16) float scw[2048];
    __shared__ __align__(16) float swn[64];
    __shared__ __align__(16) float sbn[64];
    __shared__ float srow[128*65];   // per-thread: [0..31]=fv, [32..63]=scratch
    int t = threadIdx.x;
    for (int i=t;i<2048;i+=128) scw[i]=cw[i];
    if (t<64){ swn[t]=l1w[t]; sbn[t]=l1b[t]; }
    size_t pt = (size_t)blockIdx.x*128 + t;
    float* fvp  = srow + t*65;
    float* rawp = fvp + 32;
    {
        const float4* fp = (const float4*)(g_fused + pt*32);
        #pragma unroll
        for (int q=0;q<8;q++){
            float4 f=fp[q];
            fvp[4*q]=f.x; fvp[4*q+1]=f.y; fvp[4*q+2]=f.z; fvp[4*q+3]=f.w;
        }
    }
    __syncthreads();

    u64 acc[16];
    // ---- pass 1: outputs 0..31 ----
    #pragma unroll
    for (int i=0;i<16;i++) acc[i]=0ull;
    #pragma unroll 4
    for (int j=0;j<32;j++){
        float fj = fvp[j];
        u64 fjp = pk2(fj,fj);
        const ulonglong2* cr = (const ulonglong2*)(scw + j*64);
        #pragma unroll
        for (int q=0;q<8;q++){
            ulonglong2 w=cr[q];
            acc[2*q]   = fma2_(fjp, w.x, acc[2*q]);
            acc[2*q+1] = fma2_(fjp, w.y, acc[2*q+1]);
        }
    }
    float s1;
    {
        u64 a8[8];
        #pragma unroll
        for (int i=0;i<8;i++) a8[i]=add2_(acc[2*i],acc[2*i+1]);
        u64 a4a=add2_(a8[0],a8[1]), a4b=add2_(a8[2],a8[3]);
        u64 a4c=add2_(a8[4],a8[5]), a4d=add2_(a8[6],a8[7]);
        u64 tt=add2_(add2_(a4a,a4b),add2_(a4c,a4d));
        float lo,hi; up2(tt,lo,hi); s1=lo+hi;
    }
    #pragma unroll
    for (int i=0;i<16;i++){
        float lo,hi; up2(acc[i],lo,hi);
        rawp[2*i]=lo; rawp[2*i+1]=hi;
    }
    // ---- pass 2: outputs 32..63 (kept packed in acc) ----
    #pragma unroll
    for (int i=0;i<16;i++) acc[i]=0ull;
    #pragma unroll 4
    for (int j=0;j<32;j++){
        float fj = fvp[j];
        u64 fjp = pk2(fj,fj);
        const ulonglong2* cr = (const ulonglong2*)(scw + j*64 + 32);
        #pragma unroll
        for (int q=0;q<8;q++){
            ulonglong2 w=cr[q];
            acc[2*q]   = fma2_(fjp, w.x, acc[2*q]);
            acc[2*q+1] = fma2_(fjp, w.y, acc[2*q+1]);
        }
    }
    float s2;
    {
        u64 a8[8];
        #pragma unroll
        for (int i=0;i<8;i++) a8[i]=add2_(acc[2*i],acc[2*i+1]);
        u64 a4a=add2_(a8[0],a8[1]), a4b=add2_(a8[2],a8[3]);
        u64 a4c=add2_(a8[4],a8[5]), a4d=add2_(a8[6],a8[7]);
        u64 tt=add2_(add2_(a4a,a4b),add2_(a4c,a4d));
        float lo,hi; up2(tt,lo,hi); s2=lo+hi;
    }
    float m = (s1+s2)*(1.f/64.f);
    u64 mn = pk2(-m,-m);
    // variance
    u64 va=0ull;
    #pragma unroll
    for (int i=0;i<16;i++){
        u64 d = add2_(acc[i],mn);
        va = fma2_(d,d,va);
    }
    float vlo,vhi; up2(va,vlo,vhi);
    float vv = vlo+vhi;
    #pragma unroll
    for (int k=0;k<32;k++){
        float d = rawp[k]-m;
        vv = fmaf(d,d,vv);
    }
    float rinv = rsqrtf(vv*(1.f/64.f)+1e-5f);
    // LN: upper in place (packed), mx over all 64
    u64 rp = pk2(rinv,rinv);
    const u64* wnp = (const u64*)(swn+32);
    const u64* bnp = (const u64*)(sbn+32);
    float mx=-1e30f;
    #pragma unroll
    for (int i=0;i<16;i++){
        u64 v = fma2_(mul2_(add2_(acc[i],mn),rp), wnp[i], bnp[i]);
        acc[i]=v;
        float lo,hi; up2(v,lo,hi);
        mx=fmaxf(mx,fmaxf(lo,hi));
    }
    #pragma unroll
    for (int k=0;k<32;k++){
        float val = (rawp[k]-m)*rinv*swn[k]+sbn[k];
        mx=fmaxf(mx,val);
    }
    // exp + sum; lower e parked back in rawp, upper e repacked into acc
    float sum=0.f;
    #pragma unroll
    for (int k=0;k<32;k++){
        float val = (rawp[k]-m)*rinv*swn[k]+sbn[k];
        float e = __expf(val-mx);
        rawp[k]=e; sum+=e;
    }
    #pragma unroll
    for (int i=0;i<16;i++){
        float lo,hi; up2(acc[i],lo,hi);
        float e0=__expf(lo-mx), e1=__expf(hi-mx);
        sum+=e0+e1;
        acc[i]=pk2(e0,e1);
    }
    float mkf = (mask[pt]!=0) ? 1.f : 0.f;
    float scl = mkf/sum;
    float4* ap = (float4*)(g_act + pt*64);
    #pragma unroll
    for (int q=0;q<8;q++)
        ap[q] = make_float4(rawp[4*q]*scl, rawp[4*q+1]*scl,
                            rawp[4*q+2]*scl, rawp[4*q+3]*scl);
    #pragma unroll
    for (int q=0;q<8;q++){
        float a0,a1,a2,a3;
        up2(acc[2*q],   a0,a1);
        up2(acc[2*q+1], a2,a3);
        ap[8+q] = make_float4(a0*scl,a1*scl,a2*scl,a3*scl);
    }
}

// ---------------------------------------------------------------------------
// Kernel C: split-K partials of vlad[b][d][k] = sum_n fused[n][d]*act[n][k]
// ---------------------------------------------------------------------------
__global__ void __launch_bounds__(256) vladK(){
    int b = blockIdx.y, chunk = blockIdx.x, t = threadIdx.x;
    __shared__ __align__(16) float fs[64*32];
    __shared__ __align__(16) float as_[64*64];
    __shared__ float sasum[256];
    int k0 = (t & 15) * 4;
    int d0 = (t >> 4) * 2;
    float acc[2][4];
    #pragma unroll
    for (int i=0;i<2;i++)
        #pragma unroll
        for (int j=0;j<4;j++) acc[i][j]=0.f;
    float asum = 0.f;
    int pa_off = t >> 6;
    int pa_col = t & 63;
    const float* fbase = g_fused + ((size_t)b*NPTS + (size_t)chunk*CHPTS)*32;
    const float* abase = g_act   + ((size_t)b*NPTS + (size_t)chunk*CHPTS)*64;

    for (int tile=0; tile<CHPTS/64; tile++){
        __syncthreads();
        {
            const float4* fsrc = (const float4*)(fbase + tile*64*32);
            const float4* asrc = (const float4*)(abase + tile*64*64);
            float4* fdst = (float4*)fs;
            float4* adst = (float4*)as_;
            #pragma unroll
            for (int i=0;i<2;i++) fdst[t + 256*i] = fsrc[t + 256*i];
            #pragma unroll
            for (int i=0;i<4;i++) adst[t + 256*i] = asrc[t + 256*i];
        }
        __syncthreads();
        #pragma unroll 4
        for (int p=0;p<64;p++){
            float2 f = *(const float2*)(fs  + p*32 + d0);
            float4 a = *(const float4*)(as_ + p*64 + k0);
            acc[0][0] += f.x*a.x; acc[0][1] += f.x*a.y;
            acc[0][2] += f.x*a.z; acc[0][3] += f.x*a.w;
            acc[1][0] += f.y*a.x; acc[1][1] += f.y*a.y;
            acc[1][2] += f.y*a.z; acc[1][3] += f.y*a.w;
        }
        #pragma unroll
        for (int i=0;i<16;i++)
            asum += as_[(pa_off + 4*i)*64 + pa_col];
    }
    float* pv = g_pv + ((size_t)b*NCHUNK+chunk)*2048;
    *(float4*)(pv + (d0  )*64 + k0) = make_float4(acc[0][0],acc[0][1],acc[0][2],acc[0][3]);
    *(float4*)(pv + (d0+1)*64 + k0) = make_float4(acc[1][0],acc[1][1],acc[1][2],acc[1][3]);
    sasum[t] = asum;
    __syncthreads();
    if (t<64)
        g_pa[((size_t)b*NCHUNK+chunk)*64+t] =
            sasum[t] + sasum[64+t] + sasum[128+t] + sasum[192+t];
}

// ---------------------------------------------------------------------------
// Kernel C2: reduce g_pv over chunks -> g_vl (B,2048).
// ---------------------------------------------------------------------------
__global__ void __launch_bounds__(256) redK(){
    __shared__ float red[256];
    int b = blockIdx.y;
    int cell0 = blockIdx.x * 16;
    int t = threadIdx.x;
    int ci = t & 15;
    int cg = t >> 4;
    const float* src = g_pv + (size_t)b*NCHUNK*2048 + cell0 + ci;
    float s = 0.f;
    #pragma unroll
    for (int c=0;c<8;c++) s += src[(size_t)(cg*8+c)*2048];
    red[t]=s; __syncthreads();
    #pragma unroll
    for (int o=128;o>=16;o>>=1){
        if (t<o) red[t]+=red[t+o];
        __syncthreads();
    }
    if (t<16) g_vl[b*2048 + cell0 + t] = red[t];
}

// ---------------------------------------------------------------------------
// Kernel D1: per-batch normalize. grid (B), 256 threads.
// ---------------------------------------------------------------------------
__global__ void __launch_bounds__(256) normK(const float* __restrict__ cw2){
    int b = blockIdx.x, t = threadIdx.x;
    __shared__ float vl[2048];
    __shared__ float asums[64];
    __shared__ float red[256];
    __shared__ float scs;
    if (t<64){
        float a=0.f;
        #pragma unroll 8
        for (int c=0;c<NCHUNK;c++) a += g_pa[((size_t)b*NCHUNK+c)*64+t];
        asums[t]=a;
    }
    __syncthreads();
    #pragma unroll
    for (int s=0;s<8;s++){
        int cell=t+256*s;
        vl[cell] = g_vl[b*2048+cell] - asums[cell&63]*cw2[cell];
    }
    __syncthreads();
    if (t<64){
        float nsq=0.f;
        for (int d=0; d<32; d++){ float v=vl[d*64+t]; nsq += v*v; }
        asums[t] = 1.f/fmaxf(sqrtf(nsq), 1e-12f);
    }
    __syncthreads();
    float lsq=0.f;
    #pragma unroll
    for (int s=0;s<8;s++){
        int cell=t+256*s;
        float v = vl[cell]*asums[cell&63];
        vl[cell]=v; lsq += v*v;
    }
    red[t]=lsq; __syncthreads();
    for (int o=128;o>0;o>>=1){ if (t<o) red[t]+=red[t+o]; __syncthreads(); }
    if (t==0) scs = 1.f/fmaxf(sqrtf(red[0]),1e-12f);
    __syncthreads();
    float scale = scs;
    #pragma unroll
    for (int s=0;s<8;s++)
        g_vl[b*2048 + t+256*s] = vl[t+256*s]*scale;
}

// ---------------------------------------------------------------------------
// Kernel D2: out = vlad @ hw (2048 -> 256). grid (8, B), 256 thr.
// ---------------------------------------------------------------------------
__global__ void __launch_bounds__(256) outK(const float* __restrict__ hw){
    int b = blockIdx.y, c0 = blockIdx.x*32, t = threadIdx.x;
    int col = t & 31, seg = t >> 5;
    __shared__ float vls[2048];
    __shared__ float red[256];
    for (int i=t;i<2048;i+=256) vls[i]=g_vl[b*2048+i];
    __syncthreads();
    float s=0.f;
    const float* hp = hw + c0 + col;
    int i0 = seg*256;
    #pragma unroll 4
    for (int i=i0;i<i0+256;i++) s += vls[i]*hp[(size_t)i*256];
    red[t]=s; __syncthreads();
    if (t<32){
        float o=0.f;
        #pragma unroll
        for (int g2=0; g2<8; g2++) o += red[g2*32+t];
        g_out[b*256+c0+t]=o;
    }
}

// ---------------------------------------------------------------------------
// Kernel D3: gates = sigmoid(LN(out @ gw)); outp = out * gates. grid (B).
// ---------------------------------------------------------------------------
__global__ void __launch_bounds__(256) gateK(const float* __restrict__ gw,
    const float* __restrict__ glnw, const float* __restrict__ glnb,
    float* __restrict__ outp)
{
    int b = blockIdx.x, t = threadIdx.x;
    __shared__ float outs[256];
    __shared__ float red[256];
    outs[t]=g_out[b*256+t]; __syncthreads();
    float ov = outs[t];
    float gv=0.f;
    #pragma unroll 4
    for (int i=0;i<256;i++) gv += outs[i]*gw[i*256+t];
    red[t]=gv; __syncthreads();
    for (int o=128;o>0;o>>=1){ if (t<o) red[t]+=red[t+o]; __syncthreads(); }
    float m = red[0]*(1.f/256.f);
    __syncthreads();
    float dv = gv-m;
    red[t]=dv*dv; __syncthreads();
    for (int o=128;o>0;o>>=1){ if (t<o) red[t]+=red[t+o]; __syncthreads(); }
    float var = red[0]*(1.f/256.f);
    float gn = (gv-m)*rsqrtf(var+1e-5f)*glnw[t]+glnb[t];
    outp[b*256+t] = ov * sigmoidf_(gn);
}

// ---------------------------------------------------------------------------
// launch
// ---------------------------------------------------------------------------
extern "C" void kernel_launch(void* const* d_in, const int* in_sizes, int n_in,
                              void* d_out, int out_size)
{
    const float* xyz   = (const float*)d_in[0];
    const float* g14d  = (const float*)d_in[1];
    const float* vfeat = (const float*)d_in[2];
    const float* ext   = (const float*)d_in[3];
    const float* intr  = (const float*)d_in[4];
    const float* offs  = (const float*)d_in[5];
    const int*   mask  = (const int*)d_in[6];
    const float* gate_w1 = (const float*)d_in[7];
    const float* gate_b1 = (const float*)d_in[8];
    const float* gate_w2 = (const float*)d_in[9];
    const float* gate_b2 = (const float*)d_in[10];
    const float* bn_w1   = (const float*)d_in[11];
    const float* bn_b1   = (const float*)d_in[12];
    const float* bn_w2   = (const float*)d_in[13];
    const float* bn_b2   = (const float*)d_in[14];
    const float* bn_ln_w = (const float*)d_in[15];
    const float* bn_ln_b = (const float*)d_in[16];
    const float* cw      = (const float*)d_in[17];
    const float* cw2     = (const float*)d_in[18];
    const float* hw      = (const float*)d_in[19];
    const float* ln1_w   = (const float*)d_in[20];
    const float* ln1_b   = (const float*)d_in[21];
    const float* gw      = (const float*)d_in[22];
    const float* gln_w   = (const float*)d_in[23];
    const float* gln_b   = (const float*)d_in[24];
    float* out = (float*)d_out;

    projK<<<dim3(BATCH*NVIEW, NPIX/128), 256>>>(vfeat, bn_w1);
    pointK<<<dim3(NPTS/128, BATCH), 128>>>(xyz, g14d, ext, intr, offs, mask,
        bn_b1, bn_w2, bn_b2, bn_ln_w, bn_ln_b,
        gate_w1, gate_b1, gate_w2, gate_b2);
    actK<<<dim3((BATCH*NPTS)/128), 128>>>(cw, ln1_w, ln1_b, mask);
    vladK<<<dim3(NCHUNK, BATCH), 256>>>();
    redK<<<dim3(128, BATCH), 256>>>();
    normK<<<BATCH, 256>>>(cw2);
    outK<<<dim3(8, BATCH), 256>>>(hw);
    gateK<<<BATCH, 256>>>(gw, gln_w, gln_b, out);
}

// round 16
// speedup vs baseline: 1.1613x; 1.1442x over previous
#include <cuda_runtime.h>
#include <cuda_bf16.h>
#include <math.h>

#define BATCH 4
#define NPTS 16384
#define NVIEW 6
#define CCH 384
#define HH 32
#define WW 32
#define NPIX (HH*WW)
#define NCHUNK 128
#define CHPTS (NPTS/NCHUNK)   // 128

typedef unsigned long long u64;

// scratch (static device globals; no allocation anywhere)
__device__ __align__(16) float g_proj [BATCH*NVIEW*NPIX*64];   // 6.3 MB
__device__ __align__(16) float g_fused[BATCH*NPTS*32];         // 8 MB
__device__ __align__(16) float g_act  [BATCH*NPTS*64];         // 16 MB
__device__ __align__(16) float g_pv   [BATCH*NCHUNK*2048];     // 4 MB
__device__ __align__(16) float g_pa   [BATCH*NCHUNK*64];
__device__ __align__(16) float g_vl   [BATCH*2048];
__device__ __align__(16) float g_out  [BATCH*256];

// Branchless erf-based GELU: A&S 7.1.26 (max abs err ~1.5e-7), MUFU-backed.
__device__ __forceinline__ float geluf(float x){
    float xe = x*0.70710678118654752f;
    float ax = fabsf(xe);
    float t  = __fdividef(1.f, fmaf(0.3275911f, ax, 1.f));
    float p  = t*fmaf(t, fmaf(t, fmaf(t, fmaf(t, 1.061405429f, -1.453152027f),
                 1.421413741f), -0.284496736f), 0.254829592f);
    float e  = __expf(-ax*ax);
    float er = fmaf(-p, e, 1.f);
    er = copysignf(er, xe);
    return 0.5f*x*(1.f+er);
}
__device__ __forceinline__ float sigmoidf_(float x){
    return 1.f/(1.f+expf(-x));
}
// ---- packed f32x2 helpers (Blackwell; ptxas won't emit from C++) ----
__device__ __forceinline__ u64 pk2(float lo, float hi){
    u64 r; asm("mov.b64 %0,{%1,%2};" : "=l"(r) : "f"(lo), "f"(hi)); return r;
}
__device__ __forceinline__ void up2(u64 v, float& lo, float& hi){
    asm("mov.b64 {%0,%1},%2;" : "=f"(lo), "=f"(hi) : "l"(v));
}
__device__ __forceinline__ u64 fma2_(u64 a, u64 b, u64 c){
    u64 d; asm("fma.rn.f32x2 %0,%1,%2,%3;" : "=l"(d) : "l"(a), "l"(b), "l"(c)); return d;
}
__device__ __forceinline__ u64 mul2_(u64 a, u64 b){
    u64 d; asm("mul.rn.f32x2 %0,%1,%2;" : "=l"(d) : "l"(a), "l"(b)); return d;
}
__device__ __forceinline__ u64 add2_(u64 a, u64 b){
    u64 d; asm("add.rn.f32x2 %0,%1,%2;" : "=l"(d) : "l"(a), "l"(b)); return d;
}

// ---------------------------------------------------------------------------
// Kernel A: proj[bv][pix][o] = sum_c vf[bv][c][pix] * w1[c][o]
// ---------------------------------------------------------------------------
__global__ void __launch_bounds__(256) projK(const float* __restrict__ vf,
                                             const float* __restrict__ w1){
    __shared__ __align__(16) float w1s[96*64];
    int t = threadIdx.x;
    int bv  = blockIdx.x;
    int half = t >> 7;
    int pix = blockIdx.y*128 + (t & 127);
    int og  = half*32;
    u64 acc[16];
    #pragma unroll
    for (int i=0;i<16;i++) acc[i]=0ull;
    const float* vfb = vf + (size_t)bv*CCH*NPIX;
    for (int kt=0; kt<4; kt++){
        __syncthreads();
        for (int idx=t; idx<96*64; idx+=256) w1s[idx]=w1[kt*96*64+idx];
        __syncthreads();
        #pragma unroll 2
        for (int c=0;c<96;c++){
            float v = vfb[(kt*96+c)*NPIX + pix];
            u64 vp = pk2(v,v);
            const ulonglong2* wr = (const ulonglong2*)(w1s + c*64 + og);
            #pragma unroll
            for (int q=0;q<8;q++){
                ulonglong2 w = wr[q];
                acc[2*q]   = fma2_(vp, w.x, acc[2*q]);
                acc[2*q+1] = fma2_(vp, w.y, acc[2*q+1]);
            }
        }
    }
    ulonglong2* dst = (ulonglong2*)(g_proj + ((size_t)bv*NPIX + pix)*64 + og);
    #pragma unroll
    for (int q=0;q<8;q++){
        ulonglong2 o; o.x=acc[2*q]; o.y=acc[2*q+1];
        dst[q]=o;
    }
}

// ---------------------------------------------------------------------------
// Kernel B: per-point fusion -> g_fused (B,N,32). (Unchanged from R13 best.)
// ---------------------------------------------------------------------------
__global__ void __launch_bounds__(128) pointK(
    const float* __restrict__ xyz, const float* __restrict__ g14,
    const float* __restrict__ extp, const float* __restrict__ intrp,
    const float* __restrict__ off, const int* __restrict__ mask,
    const float* __restrict__ b1, const float* __restrict__ w2,
    const float* __restrict__ b2, const float* __restrict__ lnw,
    const float* __restrict__ lnb,
    const float* __restrict__ gw1, const float* __restrict__ gb1,
    const float* __restrict__ gw2, const float* __restrict__ gb2)
{
    __shared__ __align__(16) float s_h[4*32*68];
    __shared__ __align__(16) float s_w2[64*32];
    __shared__ __align__(16) float s_b1[64];
    __shared__ __align__(16) float s_b2[32];
    __shared__ __align__(16) float s_lnw[32];
    __shared__ __align__(16) float s_lnb[32];
    __shared__ float s_ext[NVIEW*12], s_intr[NVIEW*9];
    __shared__ float s_gw1[64], s_gb1[16], s_gw2[16];
    __shared__ float s_gb2;
    __shared__ uint2 s_pix[128];
    __shared__ __align__(16) float s_wt[128*4];
    int t = threadIdx.x;
    int b = blockIdx.y;
    int n = blockIdx.x*128 + t;
    int lane = t & 31;
    int wid  = t >> 5;
    int half16 = (lane >> 4) << 4;
    int qc = lane & 15;
    for (int i=t;i<2048;i+=128) s_w2[i]=w2[i];
    if (t<64){ s_b1[t]=b1[t]; s_gw1[t]=gw1[t]; }
    if (t<32){ s_b2[t]=b2[t]; s_lnw[t]=lnw[t]; s_lnb[t]=lnb[t]; }
    if (t<16){ s_gb1[t]=gb1[t]; s_gw2[t]=gw2[t]; }
    if (t<NVIEW*12) s_ext[t]=extp[b*NVIEW*12+t];
    if (t<NVIEW*9)  s_intr[t]=intrp[b*NVIEW*9+t];
    if (t==0) s_gb2=gb2[0];
    __syncthreads();

    size_t pt = (size_t)b*NPTS + n;
    float px = xyz[pt*3+0], py = xyz[pt*3+1], pz = xyz[pt*3+2];
    const float* g = g14 + pt*14;
    float sc0 = fminf(fmaxf(g[4],0.01f),10.f);
    float sc1 = fminf(fmaxf(g[5],0.01f),10.f);
    float sc2 = fminf(fmaxf(g[6],0.01f),10.f);
    float opc = fminf(fmaxf(g[11],0.f),1.f);
    float gacc = s_gb2;
    #pragma unroll
    for (int h=0;h<16;h++){
        float z = s_gb1[h] + sc0*s_gw1[h] + sc1*s_gw1[16+h]
                + sc2*s_gw1[32+h] + opc*s_gw1[48+h];
        gacc += geluf(z)*s_gw2[h];
    }
    float gate = sigmoidf_(gacc);
    float offx = off[pt*2+0], offy = off[pt*2+1];
    bool  mk   = (mask[pt] != 0);

    u64 sumf[16];
    #pragma unroll
    for (int j=0;j<16;j++) sumf[j]=0ull;
    float summ = 0.f;
    float* hwarp = s_h + wid*(32*68);
    float* hrow  = hwarp + lane*68;
    const u64* b2p  = (const u64*)s_b2;
    const u64* lnwp = (const u64*)s_lnw;
    const u64* lnbp = (const u64*)s_lnb;

    for (int v=0; v<NVIEW; v++){
        const float* E  = s_ext  + v*12;
        const float* Km = s_intr + v*9;
        float cx = E[0]*px+E[1]*py+E[2]*pz+E[3];
        float cy = E[4]*px+E[5]*py+E[6]*pz+E[7];
        float cz = E[8]*px+E[9]*py+E[10]*pz+E[11];
        float ux = Km[0]*cx+Km[1]*cy+Km[2]*cz;
        float uy = Km[3]*cx+Km[4]*cy+Km[5]*cz;
        float uz = Km[6]*cx+Km[7]*cy+Km[8]*cz;
        float depth = fmaxf(uz, 1e-6f);
        float gx = 2.f*(ux/depth)/448.f - 1.f + offx;
        float gy = 2.f*(uy/depth)/448.f - 1.f + offy;
        bool valid = (uz>0.1f) && (fabsf(gx)<=1.f) && (fabsf(gy)<=1.f) && mk;
        float vm = valid ? 1.f : 0.f;
        float xs = fminf(fmaxf(((gx+1.f)*32.f - 1.f)*0.5f, -100.f), 100.f);
        float ys = fminf(fmaxf(((gy+1.f)*32.f - 1.f)*0.5f, -100.f), 100.f);
        float x0f = floorf(xs), y0f = floorf(ys);
        float wx = xs-x0f, wy = ys-y0f;
        int x0=(int)x0f, y0=(int)y0f;
        unsigned int xc0 = (unsigned)min(max(x0  ,0),31);
        unsigned int xc1 = (unsigned)min(max(x0+1,0),31);
        unsigned int yc0 = (unsigned)min(max(y0  ,0),31);
        unsigned int yc1 = (unsigned)min(max(y0+1,0),31);
        bool vx0 = (x0>=0)&&(x0<32),  vx1 = (x0+1>=0)&&(x0+1<32);
        bool vy0 = (y0>=0)&&(y0<32),  vy1 = (y0+1>=0)&&(y0+1<32);
        float w00 = (1.f-wx)*(1.f-wy)*((vx0&&vy0)?vm:0.f);
        float w10 = wx*(1.f-wy)      *((vx1&&vy0)?vm:0.f);
        float w01 = (1.f-wx)*wy      *((vx0&&vy1)?vm:0.f);
        float w11 = wx*wy            *((vx1&&vy1)?vm:0.f);
        s_pix[t] = make_uint2((yc0*32+xc0) | ((yc0*32+xc1)<<16),
                              (yc1*32+xc0) | ((yc1*32+xc1)<<16));
        s_wt[t*4+0]=w00; s_wt[t*4+1]=w10; s_wt[t*4+2]=w01; s_wt[t*4+3]=w11;
        __syncwarp();

        const float* pb = g_proj + (size_t)(b*NVIEW+v)*NPIX*64;
        int wbase = wid*32;
        #pragma unroll 4
        for (int s16=0; s16<16; s16++){
            int srcp = s16 + half16;
            int sidx = wbase + srcp;
            uint2 pp = s_pix[sidx];
            float4 wt = *(const float4*)(s_wt + sidx*4);
            ulonglong2 v00 = *((const ulonglong2*)(pb + (size_t)(pp.x&0xffffu)*64) + qc);
            ulonglong2 v10 = *((const ulonglong2*)(pb + (size_t)(pp.x>>16)*64) + qc);
            ulonglong2 v01 = *((const ulonglong2*)(pb + (size_t)(pp.y&0xffffu)*64) + qc);
            ulonglong2 v11 = *((const ulonglong2*)(pb + (size_t)(pp.y>>16)*64) + qc);
            u64 w00p=pk2(wt.x,wt.x), w10p=pk2(wt.y,wt.y);
            u64 w01p=pk2(wt.z,wt.z), w11p=pk2(wt.w,wt.w);
            ulonglong2 o;
            o.x = fma2_(w11p,v11.x, fma2_(w01p,v01.x, fma2_(w10p,v10.x, mul2_(w00p,v00.x))));
            o.y = fma2_(w11p,v11.y, fma2_(w01p,v01.y, fma2_(w10p,v10.y, mul2_(w00p,v00.y))));
            *(ulonglong2*)(hwarp + srcp*68 + qc*4) = o;
        }
        __syncwarp();

        u64 yp[16];
        #pragma unroll
        for (int i=0;i<16;i++) yp[i]=b2p[i];
        #pragma unroll 2
        for (int c=0;c<16;c++){
            float4 hv = *(float4*)(hrow + c*4);
            float h0=geluf(hv.x + s_b1[4*c+0]);
            float h1=geluf(hv.y + s_b1[4*c+1]);
            float h2=geluf(hv.z + s_b1[4*c+2]);
            float h3=geluf(hv.w + s_b1[4*c+3]);
            u64 h0p=pk2(h0,h0), h1p=pk2(h1,h1), h2p=pk2(h2,h2), h3p=pk2(h3,h3);
            const ulonglong2* r0=(const ulonglong2*)(s_w2+(4*c  )*32);
            const ulonglong2* r1=(const ulonglong2*)(s_w2+(4*c+1)*32);
            const ulonglong2* r2=(const ulonglong2*)(s_w2+(4*c+2)*32);
            const ulonglong2* r3=(const ulonglong2*)(s_w2+(4*c+3)*32);
            #pragma unroll
            for (int q=0;q<8;q++){
                ulonglong2 w0=r0[q],w1=r1[q],w2v=r2[q],w3=r3[q];
                yp[2*q]   = fma2_(h0p,w0.x,fma2_(h1p,w1.x,fma2_(h2p,w2v.x,fma2_(h3p,w3.x,yp[2*q]))));
                yp[2*q+1] = fma2_(h0p,w0.y,fma2_(h1p,w1.y,fma2_(h2p,w2v.y,fma2_(h3p,w3.y,yp[2*q+1]))));
            }
        }
        u64 t8[8];
        #pragma unroll
        for (int i=0;i<8;i++) t8[i]=add2_(yp[2*i],yp[2*i+1]);
        u64 t4a=add2_(t8[0],t8[1]), t4b=add2_(t8[2],t8[3]);
        u64 t4c=add2_(t8[4],t8[5]), t4d=add2_(t8[6],t8[7]);
        u64 t2a=add2_(t4a,t4b),     t2b=add2_(t4c,t4d);
        u64 tt = add2_(t2a,t2b);
        float slo,shi; up2(tt,slo,shi);
        float m = (slo+shi)*(1.f/32.f);
        u64 mn = pk2(-m,-m);
        u64 vacc = 0ull;
        #pragma unroll
        for (int i=0;i<16;i++){
            u64 d = add2_(yp[i], mn);
            vacc = fma2_(d,d,vacc);
        }
        float vlo,vhi; up2(vacc,vlo,vhi);
        float var = (vlo+vhi)*(1.f/32.f);
        float rinv = rsqrtf(var + 1e-5f);
        float gv = gate*vm;
        summ += vm;
        u64 rp = pk2(rinv,rinv), gp = pk2(gv,gv);
        #pragma unroll
        for (int i=0;i<16;i++){
            u64 t1 = add2_(yp[i], mn);
            u64 t2 = mul2_(t1, rp);
            u64 t3 = fma2_(t2, lnwp[i], lnbp[i]);
            sumf[i] = fma2_(t3, gp, sumf[i]);
        }
    }
    float fin = 1.f/(summ + 1e-6f);
    float4* fo = (float4*)(g_fused + pt*32);
    #pragma unroll
    for (int q=0;q<8;q++){
        float a0,a1,a2,a3;
        up2(sumf[2*q],   a0, a1);
        up2(sumf[2*q+1], a2, a3);
        fo[q] = make_float4(a0*fin, a1*fin, a2*fin, a3*fin);
    }
}

// ---------------------------------------------------------------------------
// Kernel B2: act = softmax(LN(fused @ cw)) * mask  -> g_act (B,N,64)
// (R13 register version.)
// ---------------------------------------------------------------------------
__global__ void __launch_bounds__(128) actK(const float* __restrict__ cw,
    const float* __restrict__ l1w, const float* __restrict__ l1b,
    const int* __restrict__ mask)
{
    __shared__ __align__(16) float scw[2048];
    __shared__ float swn[64], sbn[64];
    int t = threadIdx.x;
    for (int i=t;i<2048;i+=128) scw[i]=cw[i];
    if (t<64){ swn[t]=l1w[t]; sbn[t]=l1b[t]; }
    __syncthreads();
    size_t pt = (size_t)blockIdx.x*128 + t;
    float fv[32];
    const float4* fp = (const float4*)(g_fused + pt*32);
    #pragma unroll
    for (int q=0;q<8;q++){
        float4 f=fp[q];
        fv[4*q]=f.x; fv[4*q+1]=f.y; fv[4*q+2]=f.z; fv[4*q+3]=f.w;
    }
    u64 rowp[32];
    #pragma unroll
    for (int i=0;i<32;i++) rowp[i]=0ull;
    #pragma unroll
    for (int j=0;j<32;j++){
        u64 fjp = pk2(fv[j],fv[j]);
        const ulonglong2* cr = (const ulonglong2*)(scw + j*64);
        #pragma unroll
        for (int q=0;q<16;q++){
            ulonglong2 w=cr[q];
            rowp[2*q]   = fma2_(fjp, w.x, rowp[2*q]);
            rowp[2*q+1] = fma2_(fjp, w.y, rowp[2*q+1]);
        }
    }
    float row[64];
    #pragma unroll
    for (int i=0;i<32;i++) up2(rowp[i], row[2*i], row[2*i+1]);
    float m=0.f;
    #pragma unroll
    for (int k=0;k<64;k++) m+=row[k];
    m *= (1.f/64.f);
    float var=0.f;
    #pragma unroll
    for (int k=0;k<64;k++){ float d=row[k]-m; var+=d*d; }
    var *= (1.f/64.f);
    float rinv = rsqrtf(var+1e-5f);
    float mx=-1e30f;
    #pragma unroll
    for (int k=0;k<64;k++){
        float val=(row[k]-m)*rinv*swn[k]+sbn[k];
        row[k]=val;
        mx=fmaxf(mx,val);
    }
    float sum=0.f;
    #pragma unroll
    for (int k=0;k<64;k++){
        float e=__expf(row[k]-mx);
        row[k]=e; sum+=e;
    }
    float mkf = (mask[pt]!=0) ? 1.f : 0.f;
    float scl = mkf/sum;
    float4* ap = (float4*)(g_act + pt*64);
    #pragma unroll
    for (int q=0;q<16;q++)
        ap[q] = make_float4(row[4*q]*scl,row[4*q+1]*scl,row[4*q+2]*scl,row[4*q+3]*scl);
}

// ---------------------------------------------------------------------------
// Kernel C: split-K partials of vlad[b][d][k] = sum_n fused[n][d]*act[n][k]
// ---------------------------------------------------------------------------
__global__ void __launch_bounds__(256) vladK(){
    int b = blockIdx.y, chunk = blockIdx.x, t = threadIdx.x;
    __shared__ __align__(16) float fs[64*32];
    __shared__ __align__(16) float as_[64*64];
    __shared__ float sasum[256];
    int k0 = (t & 15) * 4;
    int d0 = (t >> 4) * 2;
    float acc[2][4];
    #pragma unroll
    for (int i=0;i<2;i++)
        #pragma unroll
        for (int j=0;j<4;j++) acc[i][j]=0.f;
    float asum = 0.f;
    int pa_off = t >> 6;
    int pa_col = t & 63;
    const float* fbase = g_fused + ((size_t)b*NPTS + (size_t)chunk*CHPTS)*32;
    const float* abase = g_act   + ((size_t)b*NPTS + (size_t)chunk*CHPTS)*64;

    for (int tile=0; tile<CHPTS/64; tile++){
        __syncthreads();
        {
            const float4* fsrc = (const float4*)(fbase + tile*64*32);
            const float4* asrc = (const float4*)(abase + tile*64*64);
            float4* fdst = (float4*)fs;
            float4* adst = (float4*)as_;
            #pragma unroll
            for (int i=0;i<2;i++) fdst[t + 256*i] = fsrc[t + 256*i];
            #pragma unroll
            for (int i=0;i<4;i++) adst[t + 256*i] = asrc[t + 256*i];
        }
        __syncthreads();
        #pragma unroll 4
        for (int p=0;p<64;p++){
            float2 f = *(const float2*)(fs  + p*32 + d0);
            float4 a = *(const float4*)(as_ + p*64 + k0);
            acc[0][0] += f.x*a.x; acc[0][1] += f.x*a.y;
            acc[0][2] += f.x*a.z; acc[0][3] += f.x*a.w;
            acc[1][0] += f.y*a.x; acc[1][1] += f.y*a.y;
            acc[1][2] += f.y*a.z; acc[1][3] += f.y*a.w;
        }
        #pragma unroll
        for (int i=0;i<16;i++)
            asum += as_[(pa_off + 4*i)*64 + pa_col];
    }
    float* pv = g_pv + ((size_t)b*NCHUNK+chunk)*2048;
    *(float4*)(pv + (d0  )*64 + k0) = make_float4(acc[0][0],acc[0][1],acc[0][2],acc[0][3]);
    *(float4*)(pv + (d0+1)*64 + k0) = make_float4(acc[1][0],acc[1][1],acc[1][2],acc[1][3]);
    sasum[t] = asum;
    __syncthreads();
    if (t<64)
        g_pa[((size_t)b*NCHUNK+chunk)*64+t] =
            sasum[t] + sasum[64+t] + sasum[128+t] + sasum[192+t];
}

// ---------------------------------------------------------------------------
// Kernel C2: reduce g_pv over chunks -> g_vl (B,2048).
// ---------------------------------------------------------------------------
__global__ void __launch_bounds__(256) redK(){
    __shared__ float red[256];
    int b = blockIdx.y;
    int cell0 = blockIdx.x * 16;
    int t = threadIdx.x;
    int ci = t & 15;
    int cg = t >> 4;
    const float* src = g_pv + (size_t)b*NCHUNK*2048 + cell0 + ci;
    float s = 0.f;
    #pragma unroll
    for (int c=0;c<8;c++) s += src[(size_t)(cg*8+c)*2048];
    red[t]=s; __syncthreads();
    #pragma unroll
    for (int o=128;o>=16;o>>=1){
        if (t<o) red[t]+=red[t+o];
        __syncthreads();
    }
    if (t<16) g_vl[b*2048 + cell0 + t] = red[t];
}

// ---------------------------------------------------------------------------
// Kernel D1: per-batch normalize. grid (B), 256 threads.
// g_pa reduction spread over all 256 threads (32 loads each).
// ---------------------------------------------------------------------------
__global__ void __launch_bounds__(256) normK(const float* __restrict__ cw2){
    int b = blockIdx.x, t = threadIdx.x;
    __shared__ float vl[2048];
    __shared__ float asums[64];
    __shared__ float red[256];
    __shared__ float scs;
    {
        int col = t & 63, grp = t >> 6;    // 4 groups of 32 chunks
        float a=0.f;
        #pragma unroll 8
        for (int c=0;c<32;c++)
            a += g_pa[((size_t)b*NCHUNK + grp*32 + c)*64 + col];
        red[t]=a;
    }
    __syncthreads();
    if (t<64)
        asums[t] = red[t] + red[64+t] + red[128+t] + red[192+t];
    __syncthreads();
    #pragma unroll
    for (int s=0;s<8;s++){
        int cell=t+256*s;
        vl[cell] = g_vl[b*2048+cell] - asums[cell&63]*cw2[cell];
    }
    __syncthreads();
    if (t<64){
        float nsq=0.f;
        for (int d=0; d<32; d++){ float v=vl[d*64+t]; nsq += v*v; }
        asums[t] = 1.f/fmaxf(sqrtf(nsq), 1e-12f);
    }
    __syncthreads();
    float lsq=0.f;
    #pragma unroll
    for (int s=0;s<8;s++){
        int cell=t+256*s;
        float v = vl[cell]*asums[cell&63];
        vl[cell]=v; lsq += v*v;
    }
    red[t]=lsq; __syncthreads();
    for (int o=128;o>0;o>>=1){ if (t<o) red[t]+=red[t+o]; __syncthreads(); }
    if (t==0) scs = 1.f/fmaxf(sqrtf(red[0]),1e-12f);
    __syncthreads();
    float scale = scs;
    #pragma unroll
    for (int s=0;s<8;s++)
        g_vl[b*2048 + t+256*s] = vl[t+256*s]*scale;
}

// ---------------------------------------------------------------------------
// Kernel D2: out = vlad @ hw (2048 -> 256). grid (32, B), 256 thr:
// 8 cols x 32 row-segments of 64 per block. ~1 full wave, 64 loads/thread.
// ---------------------------------------------------------------------------
__global__ void __launch_bounds__(256) outK(const float* __restrict__ hw){
    int b = blockIdx.y, c0 = blockIdx.x*8, t = threadIdx.x;
    int col = t & 7, seg = t >> 3;       // 32 segs of 64 rows
    __shared__ float vls[2048];
    __shared__ float red[256];
    for (int i=t;i<2048;i+=256) vls[i]=g_vl[b*2048+i];
    __syncthreads();
    float s=0.f;
    const float* hp = hw + c0 + col;
    int i0 = seg*64;
    #pragma unroll 8
    for (int i=i0;i<i0+64;i++) s += vls[i]*hp[(size_t)i*256];
    red[t]=s; __syncthreads();
    if (t<8){
        float o=0.f;
        #pragma unroll
        for (int g2=0; g2<32; g2++) o += red[g2*8+t];
        g_out[b*256+c0+t]=o;
    }
}

// ---------------------------------------------------------------------------
// Kernel D3: gates = sigmoid(LN(out @ gw)); outp = out * gates.
// grid (B), 1024 threads: col = t&255, row-quarter = t>>8 (64 rows each).
// ---------------------------------------------------------------------------
__global__ void __launch_bounds__(1024) gateK(const float* __restrict__ gw,
    const float* __restrict__ glnw, const float* __restrict__ glnb,
    float* __restrict__ outp)
{
    int b = blockIdx.x, t = threadIdx.x;
    __shared__ float outs[256];
    __shared__ float red2[1024];
    __shared__ float red[256];
    if (t<256) outs[t]=g_out[b*256+t];
    __syncthreads();
    int col = t & 255, q = t >> 8;       // 4 quarters of 64 rows
    float gv=0.f;
    const float* gp = gw + col;
    int i0 = q*64;
    #pragma unroll 8
    for (int i=i0;i<i0+64;i++) gv += outs[i]*gp[(size_t)i*256];
    red2[t]=gv; __syncthreads();
    float gvf=0.f;
    if (t<256) gvf = red2[t]+red2[256+t]+red2[512+t]+red2[768+t];
    if (t<256) red[t]=gvf;
    __syncthreads();
    for (int o=128;o>0;o>>=1){ if (t<o) red[t]+=red[t+o]; __syncthreads(); }
    float m = red[0]*(1.f/256.f);
    __syncthreads();
    if (t<256){ float dv=gvf-m; red[t]=dv*dv; }
    __syncthreads();
    for (int o=128;o>0;o>>=1){ if (t<o) red[t]+=red[t+o]; __syncthreads(); }
    float var = red[0]*(1.f/256.f);
    if (t<256){
        float gn = (gvf-m)*rsqrtf(var+1e-5f)*glnw[t]+glnb[t];
        outp[b*256+t] = outs[t] * sigmoidf_(gn);
    }
}

// ---------------------------------------------------------------------------
// launch
// ---------------------------------------------------------------------------
extern "C" void kernel_launch(void* const* d_in, const int* in_sizes, int n_in,
                              void* d_out, int out_size)
{
    const float* xyz   = (const float*)d_in[0];
    const float* g14d  = (const float*)d_in[1];
    const float* vfeat = (const float*)d_in[2];
    const float* ext   = (const float*)d_in[3];
    const float* intr  = (const float*)d_in[4];
    const float* offs  = (const float*)d_in[5];
    const int*   mask  = (const int*)d_in[6];
    const float* gate_w1 = (const float*)d_in[7];
    const float* gate_b1 = (const float*)d_in[8];
    const float* gate_w2 = (const float*)d_in[9];
    const float* gate_b2 = (const float*)d_in[10];
    const float* bn_w1   = (const float*)d_in[11];
    const float* bn_b1   = (const float*)d_in[12];
    const float* bn_w2   = (const float*)d_in[13];
    const float* bn_b2   = (const float*)d_in[14];
    const float* bn_ln_w = (const float*)d_in[15];
    const float* bn_ln_b = (const float*)d_in[16];
    const float* cw      = (const float*)d_in[17];
    const float* cw2     = (const float*)d_in[18];
    const float* hw      = (const float*)d_in[19];
    const float* ln1_w   = (const float*)d_in[20];
    const float* ln1_b   = (const float*)d_in[21];
    const float* gw      = (const float*)d_in[22];
    const float* gln_w   = (const float*)d_in[23];
    const float* gln_b   = (const float*)d_in[24];
    float* out = (float*)d_out;

    projK<<<dim3(BATCH*NVIEW, NPIX/128), 256>>>(vfeat, bn_w1);
    pointK<<<dim3(NPTS/128, BATCH), 128>>>(xyz, g14d, ext, intr, offs, mask,
        bn_b1, bn_w2, bn_b2, bn_ln_w, bn_ln_b,
        gate_w1, gate_b1, gate_w2, gate_b2);
    actK<<<dim3((BATCH*NPTS)/128), 128>>>(cw, ln1_w, ln1_b, mask);
    vladK<<<dim3(NCHUNK, BATCH), 256>>>();
    redK<<<dim3(128, BATCH), 256>>>();
    normK<<<BATCH, 256>>>(cw2);
    outK<<<dim3(32, BATCH), 256>>>(hw);
    gateK<<<BATCH, 1024>>>(gw, gln_w, gln_b, out);
}